// round 12
// baseline (speedup 1.0000x reference)
#include <cuda_runtime.h>
#include <cuda_fp16.h>
#include <cstdint>

// Problem constants
#define BATCH 16
#define INCH  256
#define HWPX  2304
#define SEQ   2048
#define CTXD  128
#define EMB   256
#define NROWS (BATCH * HWPX)   // 36864 attention rows

// ======================= PTX helpers =======================
__device__ __forceinline__ uint32_t smem_u32(const void* p) {
    uint32_t a;
    asm("{ .reg .u64 t; cvta.to.shared.u64 t, %1; cvt.u32.u64 %0, t; }" : "=r"(a) : "l"(p));
    return a;
}
__device__ __forceinline__ void cp_async16(uint32_t dst, const void* src) {
    asm volatile("cp.async.cg.shared.global [%0], [%1], 16;" :: "r"(dst), "l"(src));
}
#define CP_COMMIT() asm volatile("cp.async.commit_group;" ::: "memory")
#define CP_WAIT0()  asm volatile("cp.async.wait_group 0;" ::: "memory")
#define CP_WAIT1()  asm volatile("cp.async.wait_group 1;" ::: "memory")

__device__ __forceinline__ void ldsm4(uint32_t* r, uint32_t addr) {
    asm volatile("ldmatrix.sync.aligned.m8n8.x4.shared.b16 {%0,%1,%2,%3}, [%4];"
        : "=r"(r[0]), "=r"(r[1]), "=r"(r[2]), "=r"(r[3]) : "r"(addr));
}
__device__ __forceinline__ void ldsm4t(uint32_t* r, uint32_t addr) {
    asm volatile("ldmatrix.sync.aligned.m8n8.x4.trans.shared.b16 {%0,%1,%2,%3}, [%4];"
        : "=r"(r[0]), "=r"(r[1]), "=r"(r[2]), "=r"(r[3]) : "r"(addr));
}
__device__ __forceinline__ void mma16816(float* c, const uint32_t* a, uint32_t b0, uint32_t b1) {
    asm volatile("mma.sync.aligned.m16n8k16.row.col.f32.f16.f16.f32 "
        "{%0,%1,%2,%3}, {%4,%5,%6,%7}, {%8,%9}, {%0,%1,%2,%3};"
        : "+f"(c[0]), "+f"(c[1]), "+f"(c[2]), "+f"(c[3])
        : "r"(a[0]), "r"(a[1]), "r"(a[2]), "r"(a[3]), "r"(b0), "r"(b1));
}

// ======================= scratch =======================
__device__ __align__(16) float g_Weff[EMB * INCH];
__device__ __align__(16) float g_beff[EMB];
__device__ __align__(16) __half g_Weffh[EMB * INCH];
__device__ __align__(16) __half g_Wkh[EMB * CTXD];
__device__ __align__(16) __half g_Wvh[EMB * CTXD];
__device__ __align__(16) __half g_Wouth[INCH * EMB];
__device__ __align__(16) __half g_ctx16[BATCH * SEQ * CTXD];       // 8.4 MB
__device__ __align__(16) __half g_Q[BATCH * HWPX * EMB];
__device__ __align__(16) __half g_K[BATCH * SEQ * EMB];
__device__ __align__(16) __half g_Vt[BATCH * EMB * SEQ];
__device__ __align__(16) __half g_EL[(size_t)BATCH * HWPX * SEQ];  // exp(logits) fp16, 151 MB
__device__ __align__(16) __half g_O[BATCH * HWPX * EMB];
__device__ __align__(16) float g_part[(size_t)NROWS * 32];         // deterministic row partials
__device__ __align__(16) float g_rinv[NROWS];
__device__ int g_mask_mode;

// ======================= mask dtype detection =======================
__global__ void detect_mask_kernel(const unsigned char* __restrict__ m, int nbytes) {
    __shared__ int c1, c23;
    if (threadIdx.x == 0) { c1 = 0; c23 = 0; }
    __syncthreads();
    int l1 = 0, l23 = 0;
    for (int i = threadIdx.x; i < nbytes; i += blockDim.x) {
        unsigned char v = m[i];
        if (v) { int r = i & 3; if (r == 1) l1++; else if (r >= 2) l23++; }
    }
    if (l1) atomicAdd(&c1, l1);
    if (l23) atomicAdd(&c23, l23);
    __syncthreads();
    if (threadIdx.x == 0) g_mask_mode = (c1 > 0) ? 0 : ((c23 > 0) ? 2 : 1);
}

// ======================= Weff = Wq @ W_in (fp32) =======================
__global__ void weff_kernel(const float* __restrict__ Wq, const float* __restrict__ W_in,
                            const float* __restrict__ b_in, const float* __restrict__ bq) {
    __shared__ float wqs[EMB];
    int e = blockIdx.x, c = threadIdx.x;
    wqs[c] = Wq[e * EMB + c];
    __syncthreads();
    float s = 0.f;
    #pragma unroll 8
    for (int f = 0; f < EMB; f++) s += wqs[f] * W_in[f * INCH + c];
    g_Weff[e * INCH + c] = s;
    if (c == 0) {
        float sb = 0.f;
        for (int f = 0; f < EMB; f++) sb += wqs[f] * b_in[f];
        g_beff[e] = sb + bq[e];
    }
}

__global__ void cvt_half_kernel(__half* __restrict__ d, const float* __restrict__ s, int n) {
    for (int i = blockIdx.x * blockDim.x + threadIdx.x; i < n; i += gridDim.x * blockDim.x)
        d[i] = __float2half_rn(s[i]);
}

// row inverse: rinv[i] = 1 / sum_k part[i][k]  (fixed order => deterministic)
__global__ void rowinv_kernel(const float* __restrict__ part, float* __restrict__ rinv) {
    int i = blockIdx.x * blockDim.x + threadIdx.x;
    if (i < NROWS) {
        const float* p = part + (size_t)i * 32;
        float s = 0.f;
        #pragma unroll
        for (int k = 0; k < 32; k++) s += p[k];
        rinv[i] = 1.f / s;
    }
}

// ======================= generic warp-MMA fp16 GEMM =======================
// AK: 0 = fp16 [m][k] cp.async; 1 = fp32 k-contig (convert in reg);
//     2 = fp32 m-contig source (x layout) -> smem [k][m], ldmatrix.trans
// out_kind: 0 = f32, 1 = fp16, 2 = fp16 exp() + deterministic row partial sums
struct GP {
    const void* A;
    const void* B;
    int K, lda, ldb, ldc;
    long long bsA, bsB, bsC;
    void* C;
    int out_kind;
    const float* bias; int bias_per_m;
    float alpha;
    const void* mask; long long bsMask;
    float* rs;
};

#define RS  72
#define RS2 136
#define TILE_B (128 * RS * 2)
#define TG_SMEM (4 * TILE_B)

__device__ __forceinline__ void fill16(uint32_t sbase, const __half* g, int ld, int tid) {
    #pragma unroll
    for (int i = 0; i < 4; i++) {
        int idx = tid + i * 256;
        int r = idx >> 3, c = idx & 7;
        cp_async16(sbase + (r * RS + c * 8) * 2, g + (long long)r * ld + c * 8);
    }
}
__device__ __forceinline__ void fill32k(char* sm, const float* g, int ld, int tid) {
    #pragma unroll
    for (int i = 0; i < 4; i++) {
        int c = tid + i * 256;
        int r = c >> 3, s = c & 7;
        const float4* src = (const float4*)(g + (long long)r * ld + s * 8);
        float4 u = src[0], v = src[1];
        __align__(16) __half2 h[4] = {
            __floats2half2_rn(u.x, u.y), __floats2half2_rn(u.z, u.w),
            __floats2half2_rn(v.x, v.y), __floats2half2_rn(v.z, v.w) };
        *(uint4*)(sm + (r * RS + s * 8) * 2) = *(uint4*)h;
    }
}
__device__ __forceinline__ void fill32t(char* sm, const float* g, int ldk, int tid) {
    #pragma unroll
    for (int i = 0; i < 4; i++) {
        int c = tid + i * 256;
        int r = c >> 4, s = c & 15;
        const float4* src = (const float4*)(g + (long long)r * ldk + s * 8);
        float4 u = src[0], v = src[1];
        __align__(16) __half2 h[4] = {
            __floats2half2_rn(u.x, u.y), __floats2half2_rn(u.z, u.w),
            __floats2half2_rn(v.x, v.y), __floats2half2_rn(v.z, v.w) };
        *(uint4*)(sm + (r * RS2 + s * 8) * 2) = *(uint4*)h;
    }
}

template<int AK>
__global__ void __launch_bounds__(256)
tgemm_kernel(GP p) {
    extern __shared__ char smem_raw[];
    char* smc = smem_raw;
    uint32_t sb = smem_u32(smem_raw);
    const int tid = threadIdx.x, wid = tid >> 5, lane = tid & 31;
    const int bz = blockIdx.z;
    const int m0 = blockIdx.y * 128, n0 = blockIdx.x * 128;
    const int warp_m = wid & 3, warp_n = wid >> 2;

    const int offA[2] = { 0, 2 * TILE_B };
    const int offB[2] = { TILE_B, 3 * TILE_B };

    const __half* Ah = nullptr; const float* Af = nullptr;
    if (AK == 0) Ah = (const __half*)p.A + (long long)bz * p.bsA + (long long)m0 * p.lda;
    else if (AK == 1) Af = (const float*)p.A + (long long)bz * p.bsA + (long long)m0 * p.lda;
    else Af = (const float*)p.A + (long long)bz * p.bsA + m0;
    const __half* Bh = (const __half*)p.B + (long long)bz * p.bsB + (long long)n0 * p.ldb;

    const int total = p.K >> 6;

    uint32_t aOff[2], bOff[4];
    if (AK == 2) {
        int t4 = lane >> 3, r = lane & 7;
        #pragma unroll
        for (int i = 0; i < 2; i++)
            aOff[i] = (((t4 >> 1) * 8 + r) * RS2 + warp_m * 32 + i * 16 + (t4 & 1) * 8) * 2;
    } else {
        #pragma unroll
        for (int i = 0; i < 2; i++)
            aOff[i] = ((warp_m * 32 + i * 16 + (lane & 15)) * RS + ((lane >> 4) << 3)) * 2;
    }
    #pragma unroll
    for (int j = 0; j < 4; j++)
        bOff[j] = ((warp_n * 64 + j * 16 + (lane & 7) + ((lane >> 4) << 3)) * RS
                   + (((lane >> 3) & 1) << 3)) * 2;

    float acc[2][8][4];
    #pragma unroll
    for (int i = 0; i < 2; i++)
        #pragma unroll
        for (int j = 0; j < 8; j++)
            #pragma unroll
            for (int q = 0; q < 4; q++) acc[i][j][q] = 0.f;

    auto fillA = [&](int buf, int k0) {
        if (AK == 0)      fill16(sb + offA[buf], Ah + k0, p.lda, tid);
        else if (AK == 1) fill32k(smc + offA[buf], Af + k0, p.lda, tid);
        else              fill32t(smc + offA[buf], Af + (long long)k0 * p.lda, p.lda, tid);
    };

    fillA(0, 0);
    fill16(sb + offB[0], Bh, p.ldb, tid);
    CP_COMMIT();

    for (int c = 0; c < total; c++) {
        int cur = c & 1;
        if (c + 1 < total) {
            int nb = cur ^ 1, k0 = (c + 1) << 6;
            fillA(nb, k0);
            fill16(sb + offB[nb], Bh + k0, p.ldb, tid);
            CP_COMMIT();
            CP_WAIT1();
        } else {
            CP_WAIT0();
        }
        __syncthreads();

        #pragma unroll
        for (int ks = 0; ks < 4; ks++) {
            uint32_t a[2][4];
            #pragma unroll
            for (int i = 0; i < 2; i++) {
                if (AK == 2) ldsm4t(a[i], sb + offA[cur] + aOff[i] + ks * (16 * RS2 * 2));
                else         ldsm4(a[i], sb + offA[cur] + aOff[i] + ks * 32);
            }
            #pragma unroll
            for (int jn = 0; jn < 4; jn++) {
                uint32_t b[4];
                ldsm4(b, sb + offB[cur] + bOff[jn] + ks * 32);
                #pragma unroll
                for (int i = 0; i < 2; i++) {
                    mma16816(acc[i][2 * jn],     a[i], b[0], b[1]);
                    mma16816(acc[i][2 * jn + 1], a[i], b[2], b[3]);
                }
            }
        }
        __syncthreads();
    }

    // ---- epilogue ----
    const int g = lane >> 2, t = lane & 3;
    const int mmode = p.mask ? g_mask_mode : 0;
    const int rbase = m0 + warp_m * 32;
    const int cbase = n0 + warp_n * 64;

    #pragma unroll
    for (int i = 0; i < 2; i++) {
        #pragma unroll
        for (int rr = 0; rr < 2; rr++) {
            int m = rbase + i * 16 + g + rr * 8;
            float bm = (p.bias && p.bias_per_m) ? p.bias[m] : 0.f;
            long long rowoff = (long long)bz * p.bsC + (long long)m * p.ldc;
            long long mrowoff = p.mask ? ((long long)bz * p.bsMask + (long long)m * p.ldc) : 0;
            float s_loc = 0.f;
            #pragma unroll
            for (int j = 0; j < 8; j++) {
                int n = cbase + j * 8 + 2 * t;
                float v0 = acc[i][j][rr * 2 + 0] * p.alpha + bm;
                float v1 = acc[i][j][rr * 2 + 1] * p.alpha + bm;
                if (p.bias && !p.bias_per_m) { v0 += p.bias[n]; v1 += p.bias[n + 1]; }
                if (p.mask) {
                    bool mk0, mk1;
                    if (mmode == 0) {
                        mk0 = ((const unsigned char*)p.mask)[mrowoff + n] != 0;
                        mk1 = ((const unsigned char*)p.mask)[mrowoff + n + 1] != 0;
                    } else if (mmode == 1) {
                        mk0 = ((const int*)p.mask)[mrowoff + n] != 0;
                        mk1 = ((const int*)p.mask)[mrowoff + n + 1] != 0;
                    } else {
                        mk0 = ((const float*)p.mask)[mrowoff + n] != 0.f;
                        mk1 = ((const float*)p.mask)[mrowoff + n + 1] != 0.f;
                    }
                    if (mk0) v0 = -1e9f;
                    if (mk1) v1 = -1e9f;
                }
                if (p.out_kind == 0) {
                    *(float2*)((float*)p.C + rowoff + n) = make_float2(v0, v1);
                } else if (p.out_kind == 1) {
                    __half2 pk;
                    pk.x = __float2half_rn(v0);
                    pk.y = __float2half_rn(v1);
                    *(__half2*)((__half*)p.C + rowoff + n) = pk;
                } else {
                    float e0 = __expf(v0), e1 = __expf(v1);   // masked: exp(-1e9) = 0 exactly
                    s_loc += e0 + e1;
                    __half2 pk;
                    pk.x = __float2half_rn(e0);
                    pk.y = __float2half_rn(e1);
                    *(__half2*)((__half*)p.C + rowoff + n) = pk;
                }
            }
            if (p.out_kind == 2) {
                s_loc += __shfl_xor_sync(0xffffffffu, s_loc, 1);
                s_loc += __shfl_xor_sync(0xffffffffu, s_loc, 2);
                if (t == 0)
                    p.rs[((long long)bz * HWPX + m) * 32 + blockIdx.x * 2 + warp_n] = s_loc;
            }
        }
    }
}

// ======================= fused att·V kernel =======================
// O[p,e] = sum_s (expL[p,s]*rinv[p]) * Vt[e,s]; A-fill also writes att fp32 exactly once.
// CTA tile 128 x 256(=EMB) x 64; 8 warps 4x2, warp tile 32x128. grid (1, HWPX/128, BATCH).
#define AV_A0 0
#define AV_B0 18432
#define AV_A1 (18432 + 36864)
#define AV_B1 (18432 + 36864 + 18432)
#define AV_SMEM (2 * (18432 + 36864))

__global__ void __launch_bounds__(256, 1)
attv_kernel(const __half* __restrict__ expL, const float* __restrict__ rinv,
            const __half* __restrict__ Vt, float* __restrict__ att, __half* __restrict__ O) {
    extern __shared__ char smem_raw[];
    char* smc = smem_raw;
    uint32_t sb = smem_u32(smem_raw);
    const int tid = threadIdx.x, wid = tid >> 5, lane = tid & 31;
    const int bz = blockIdx.z;
    const int m0 = blockIdx.y * 128;
    const int warp_m = wid & 3, warp_n = wid >> 2;

    const int offA[2] = { AV_A0, AV_A1 };
    const int offB[2] = { AV_B0, AV_B1 };
    const __half* Bb = Vt + (long long)bz * EMB * SEQ;

    uint32_t aOff[2], bOff[8];
    #pragma unroll
    for (int i = 0; i < 2; i++)
        aOff[i] = ((warp_m * 32 + i * 16 + (lane & 15)) * RS + ((lane >> 4) << 3)) * 2;
    #pragma unroll
    for (int j = 0; j < 8; j++)
        bOff[j] = ((warp_n * 128 + j * 16 + (lane & 7) + ((lane >> 4) << 3)) * RS
                   + (((lane >> 3) & 1) << 3)) * 2;

    float acc[2][16][4];
    #pragma unroll
    for (int i = 0; i < 2; i++)
        #pragma unroll
        for (int j = 0; j < 16; j++)
            #pragma unroll
            for (int q = 0; q < 4; q++) acc[i][j][q] = 0.f;

    auto fillA = [&](int buf, int k0) {
        #pragma unroll
        for (int i = 0; i < 4; i++) {
            int c = tid + i * 256;
            int r = c >> 3, s = c & 7;
            long long row = (long long)bz * HWPX + m0 + r;
            long long base = row * (long long)SEQ + k0 + s * 8;
            uint4 raw = *(const uint4*)(expL + base);
            float iv = rinv[row];
            __half2* hp = (__half2*)&raw;
            float f[8];
            #pragma unroll
            for (int q = 0; q < 4; q++) {
                float2 u = __half22float2(hp[q]);
                f[2 * q] = u.x * iv; f[2 * q + 1] = u.y * iv;
            }
            *(float4*)(att + base)     = make_float4(f[0], f[1], f[2], f[3]);
            *(float4*)(att + base + 4) = make_float4(f[4], f[5], f[6], f[7]);
            __align__(16) __half2 h[4];
            #pragma unroll
            for (int q = 0; q < 4; q++) h[q] = __floats2half2_rn(f[2 * q], f[2 * q + 1]);
            *(uint4*)(smc + offA[buf] + (r * RS + s * 8) * 2) = *(uint4*)h;
        }
    };
    auto fillB = [&](int buf, int k0) {
        #pragma unroll
        for (int i = 0; i < 8; i++) {
            int idx = tid + i * 256;
            int r = idx >> 3, s = idx & 7;
            cp_async16(sb + offB[buf] + (r * RS + s * 8) * 2,
                       Bb + (long long)r * SEQ + k0 + s * 8);
        }
    };

    fillA(0, 0);
    fillB(0, 0);
    CP_COMMIT();

    const int total = SEQ >> 6;   // 32
    for (int c = 0; c < total; c++) {
        int cur = c & 1;
        if (c + 1 < total) {
            int nb = cur ^ 1, k0 = (c + 1) << 6;
            fillA(nb, k0);
            fillB(nb, k0);
            CP_COMMIT();
            CP_WAIT1();
        } else {
            CP_WAIT0();
        }
        __syncthreads();

        #pragma unroll
        for (int ks = 0; ks < 4; ks++) {
            uint32_t a[2][4];
            #pragma unroll
            for (int i = 0; i < 2; i++)
                ldsm4(a[i], sb + offA[cur] + aOff[i] + ks * 32);
            #pragma unroll
            for (int jn = 0; jn < 8; jn++) {
                uint32_t b[4];
                ldsm4(b, sb + offB[cur] + bOff[jn] + ks * 32);
                #pragma unroll
                for (int i = 0; i < 2; i++) {
                    mma16816(acc[i][2 * jn],     a[i], b[0], b[1]);
                    mma16816(acc[i][2 * jn + 1], a[i], b[2], b[3]);
                }
            }
        }
        __syncthreads();
    }

    const int g = lane >> 2, t = lane & 3;
    const int rbase = m0 + warp_m * 32;
    const int cbase = warp_n * 128;
    #pragma unroll
    for (int i = 0; i < 2; i++) {
        #pragma unroll
        for (int rr = 0; rr < 2; rr++) {
            int m = rbase + i * 16 + g + rr * 8;
            long long rowoff = ((long long)bz * HWPX + m) * (long long)EMB;
            #pragma unroll
            for (int j = 0; j < 16; j++) {
                int n = cbase + j * 8 + 2 * t;
                __half2 pk;
                pk.x = __float2half_rn(acc[i][j][rr * 2 + 0]);
                pk.y = __float2half_rn(acc[i][j][rr * 2 + 1]);
                *(__half2*)(O + rowoff + n) = pk;
            }
        }
    }
}

// ======================= launch =======================
template<int AK>
static void launch_gemm(const void* A, const void* B,
                        int M, int N, int K, int lda, int ldb, int ldc,
                        long long bsA, long long bsB, long long bsC,
                        void* C, int out_kind,
                        const float* bias, int bias_per_m, float alpha,
                        const void* mask, long long bsMask, float* rs) {
    GP p;
    p.A = A; p.B = B;
    p.K = K; p.lda = lda; p.ldb = ldb; p.ldc = ldc;
    p.bsA = bsA; p.bsB = bsB; p.bsC = bsC;
    p.C = C; p.out_kind = out_kind;
    p.bias = bias; p.bias_per_m = bias_per_m; p.alpha = alpha;
    p.mask = mask; p.bsMask = bsMask; p.rs = rs;
    cudaFuncSetAttribute(tgemm_kernel<AK>, cudaFuncAttributeMaxDynamicSharedMemorySize, TG_SMEM);
    dim3 grid(N / 128, M / 128, BATCH);
    tgemm_kernel<AK><<<grid, 256, TG_SMEM>>>(p);
}

extern "C" void kernel_launch(void* const* d_in, const int* in_sizes, int n_in,
                              void* d_out, int out_size) {
    const float* x     = (const float*)d_in[0];
    const float* ctx   = (const float*)d_in[1];
    const void*  mask  = d_in[2];
    const float* W_in  = (const float*)d_in[3];
    const float* b_in  = (const float*)d_in[4];
    const float* Wq    = (const float*)d_in[5];
    const float* bq    = (const float*)d_in[6];
    const float* Wk    = (const float*)d_in[7];
    const float* bk    = (const float*)d_in[8];
    const float* Wv    = (const float*)d_in[9];
    const float* bv    = (const float*)d_in[10];
    const float* W_out = (const float*)d_in[11];
    const float* b_out = (const float*)d_in[12];

    float* out = (float*)d_out;
    float* att = out + (long long)BATCH * INCH * HWPX;

    float *pWeff, *pbeff, *pPart, *pRinv;
    __half *pWeffh, *pWkh, *pWvh, *pWoh, *pCtx16, *pQ, *pK, *pVt, *pEL, *pO;
    cudaGetSymbolAddress((void**)&pWeff, g_Weff);
    cudaGetSymbolAddress((void**)&pbeff, g_beff);
    cudaGetSymbolAddress((void**)&pWeffh, g_Weffh);
    cudaGetSymbolAddress((void**)&pWkh, g_Wkh);
    cudaGetSymbolAddress((void**)&pWvh, g_Wvh);
    cudaGetSymbolAddress((void**)&pWoh, g_Wouth);
    cudaGetSymbolAddress((void**)&pCtx16, g_ctx16);
    cudaGetSymbolAddress((void**)&pQ, g_Q);
    cudaGetSymbolAddress((void**)&pK, g_K);
    cudaGetSymbolAddress((void**)&pVt, g_Vt);
    cudaGetSymbolAddress((void**)&pEL, g_EL);
    cudaGetSymbolAddress((void**)&pO, g_O);
    cudaGetSymbolAddress((void**)&pPart, g_part);
    cudaGetSymbolAddress((void**)&pRinv, g_rinv);

    cudaFuncSetAttribute(attv_kernel, cudaFuncAttributeMaxDynamicSharedMemorySize, AV_SMEM);

    // weights + converts
    weff_kernel<<<EMB, 256>>>(Wq, W_in, b_in, bq);
    cvt_half_kernel<<<64, 256>>>(pWeffh, pWeff, EMB * INCH);
    cvt_half_kernel<<<64, 256>>>(pWkh, Wk, EMB * CTXD);
    cvt_half_kernel<<<64, 256>>>(pWvh, Wv, EMB * CTXD);
    cvt_half_kernel<<<64, 256>>>(pWoh, W_out, INCH * EMB);
    cvt_half_kernel<<<1024, 256>>>(pCtx16, ctx, BATCH * SEQ * CTXD);
    // mask dtype detection (before logits)
    int scan = 65536;
    if (in_sizes[2] < scan) scan = in_sizes[2];
    detect_mask_kernel<<<1, 256>>>((const unsigned char*)mask, scan);
    // Q-proj: Q[p,e] = x^T[p,c].Weff[e,c] + beff   (A = x fp32 trans path)
    launch_gemm<2>(x, pWeffh, HWPX, EMB, INCH,
                   HWPX, INCH, EMB, (long long)INCH * HWPX, 0, (long long)HWPX * EMB,
                   pQ, 1, pbeff, 0, 1.f, 0, 0, 0);
    // K-proj: K[s,e] = ctx[s,d].Wk[e,d] + bk   (A = ctx fp32 direct)
    launch_gemm<1>(ctx, pWkh, SEQ, EMB, CTXD,
                   CTXD, CTXD, EMB, (long long)SEQ * CTXD, 0, (long long)SEQ * EMB,
                   pK, 1, bk, 0, 1.f, 0, 0, 0);
    // V-proj: Vt[e,s] = Wv[e,d].ctx16[s,d] + bv
    launch_gemm<0>(pWvh, pCtx16, EMB, SEQ, CTXD,
                   CTXD, CTXD, SEQ, 0, (long long)SEQ * CTXD, (long long)EMB * SEQ,
                   pVt, 1, bv, 1, 1.f, 0, 0, 0);
    // logits -> exp(logits) fp16 + deterministic row partial sums
    launch_gemm<0>(pQ, pK, HWPX, SEQ, EMB,
                   EMB, EMB, SEQ, (long long)HWPX * EMB, (long long)SEQ * EMB, (long long)HWPX * SEQ,
                   pEL, 2, 0, 0, 0.0625f, mask, (long long)HWPX * SEQ, pPart);
    // row sums -> inverses
    rowinv_kernel<<<(NROWS + 255) / 256, 256>>>(pPart, pRinv);
    // fused: att fp32 write + att·V -> O fp16
    attv_kernel<<<dim3(1, HWPX / 128, BATCH), 256, AV_SMEM>>>(pEL, pRinv, pVt, att, pO);
    // out-proj: out[c,p] = W_out[c,e].O[p,e] + b_out[c]  (fp32)
    launch_gemm<0>(pWoh, pO, INCH, HWPX, EMB,
                   EMB, EMB, HWPX, 0, (long long)HWPX * EMB, (long long)INCH * HWPX,
                   out, 0, b_out, 1, 1.f, 0, 0, 0);
}

// round 14
// speedup vs baseline: 1.0296x; 1.0296x over previous
#include <cuda_runtime.h>
#include <cuda_fp16.h>
#include <cstdint>

// Problem constants
#define BATCH 16
#define INCH  256
#define HWPX  2304
#define SEQ   2048
#define CTXD  128
#define EMB   256
#define NROWS (BATCH * HWPX)   // 36864 attention rows

// ======================= PTX helpers =======================
__device__ __forceinline__ uint32_t smem_u32(const void* p) {
    uint32_t a;
    asm("{ .reg .u64 t; cvta.to.shared.u64 t, %1; cvt.u32.u64 %0, t; }" : "=r"(a) : "l"(p));
    return a;
}
__device__ __forceinline__ void cp_async16(uint32_t dst, const void* src) {
    asm volatile("cp.async.cg.shared.global [%0], [%1], 16;" :: "r"(dst), "l"(src));
}
#define CP_COMMIT() asm volatile("cp.async.commit_group;" ::: "memory")
#define CP_WAIT0()  asm volatile("cp.async.wait_group 0;" ::: "memory")
#define CP_WAIT1()  asm volatile("cp.async.wait_group 1;" ::: "memory")

__device__ __forceinline__ void ldsm4(uint32_t* r, uint32_t addr) {
    asm volatile("ldmatrix.sync.aligned.m8n8.x4.shared.b16 {%0,%1,%2,%3}, [%4];"
        : "=r"(r[0]), "=r"(r[1]), "=r"(r[2]), "=r"(r[3]) : "r"(addr));
}
__device__ __forceinline__ void ldsm4t(uint32_t* r, uint32_t addr) {
    asm volatile("ldmatrix.sync.aligned.m8n8.x4.trans.shared.b16 {%0,%1,%2,%3}, [%4];"
        : "=r"(r[0]), "=r"(r[1]), "=r"(r[2]), "=r"(r[3]) : "r"(addr));
}
__device__ __forceinline__ void mma16816(float* c, const uint32_t* a, uint32_t b0, uint32_t b1) {
    asm volatile("mma.sync.aligned.m16n8k16.row.col.f32.f16.f16.f32 "
        "{%0,%1,%2,%3}, {%4,%5,%6,%7}, {%8,%9}, {%0,%1,%2,%3};"
        : "+f"(c[0]), "+f"(c[1]), "+f"(c[2]), "+f"(c[3])
        : "r"(a[0]), "r"(a[1]), "r"(a[2]), "r"(a[3]), "r"(b0), "r"(b1));
}

// ======================= scratch =======================
__device__ __align__(16) float g_Weff[EMB * INCH];
__device__ __align__(16) float g_beff[EMB];
__device__ __align__(16) __half g_Weffh[EMB * INCH];
__device__ __align__(16) __half g_Wkh[EMB * CTXD];
__device__ __align__(16) __half g_Wvh[EMB * CTXD];
__device__ __align__(16) __half g_Wouth[INCH * EMB];
__device__ __align__(16) __half g_ctx16[BATCH * SEQ * CTXD];       // 8.4 MB
__device__ __align__(16) __half g_Q[BATCH * HWPX * EMB];
__device__ __align__(16) __half g_K[BATCH * SEQ * EMB];
__device__ __align__(16) __half g_Vt[BATCH * EMB * SEQ];
__device__ __align__(16) __half g_EL[(size_t)BATCH * HWPX * SEQ];  // exp(logits) fp16, 151 MB
__device__ __align__(16) __half g_O[BATCH * HWPX * EMB];
__device__ __align__(16) float g_part[(size_t)NROWS * 32];         // deterministic row partials
__device__ __align__(16) float g_rinv[NROWS];
__device__ int g_mask_mode;

// ======================= mask dtype detection =======================
__global__ void detect_mask_kernel(const unsigned char* __restrict__ m, int nbytes) {
    __shared__ int c1, c23;
    if (threadIdx.x == 0) { c1 = 0; c23 = 0; }
    __syncthreads();
    int l1 = 0, l23 = 0;
    for (int i = threadIdx.x; i < nbytes; i += blockDim.x) {
        unsigned char v = m[i];
        if (v) { int r = i & 3; if (r == 1) l1++; else if (r >= 2) l23++; }
    }
    if (l1) atomicAdd(&c1, l1);
    if (l23) atomicAdd(&c23, l23);
    __syncthreads();
    if (threadIdx.x == 0) g_mask_mode = (c1 > 0) ? 0 : ((c23 > 0) ? 2 : 1);
}

// ======================= Weff = Wq @ W_in (fp32) =======================
__global__ void weff_kernel(const float* __restrict__ Wq, const float* __restrict__ W_in,
                            const float* __restrict__ b_in, const float* __restrict__ bq) {
    __shared__ float wqs[EMB];
    int e = blockIdx.x, c = threadIdx.x;
    wqs[c] = Wq[e * EMB + c];
    __syncthreads();
    float s = 0.f;
    #pragma unroll 8
    for (int f = 0; f < EMB; f++) s += wqs[f] * W_in[f * INCH + c];
    g_Weff[e * INCH + c] = s;
    if (c == 0) {
        float sb = 0.f;
        for (int f = 0; f < EMB; f++) sb += wqs[f] * b_in[f];
        g_beff[e] = sb + bq[e];
    }
}

__global__ void cvt_half_kernel(__half* __restrict__ d, const float* __restrict__ s, int n) {
    for (int i = blockIdx.x * blockDim.x + threadIdx.x; i < n; i += gridDim.x * blockDim.x)
        d[i] = __float2half_rn(s[i]);
}

// row inverse: rinv[i] = 1 / sum_k part[i][k]  (fixed order => deterministic)
__global__ void rowinv_kernel(const float* __restrict__ part, float* __restrict__ rinv) {
    int i = blockIdx.x * blockDim.x + threadIdx.x;
    if (i < NROWS) {
        const float* p = part + (size_t)i * 32;
        float s = 0.f;
        #pragma unroll
        for (int k = 0; k < 32; k++) s += p[k];
        rinv[i] = 1.f / s;
    }
}

// att fp32 = expL * rinv  (pure streaming; one block per row, 8 elems/thread)
__global__ void __launch_bounds__(256) normatt_kernel(const __half* __restrict__ expL,
                                                      const float* __restrict__ rinv,
                                                      float* __restrict__ att) {
    long long row = blockIdx.x;
    const int t = threadIdx.x;
    float iv = rinv[row];
    uint4 raw = ((const uint4*)(expL + row * SEQ))[t];
    __half2* hp = (__half2*)&raw;
    float f[8];
    #pragma unroll
    for (int i = 0; i < 4; i++) {
        float2 u = __half22float2(hp[i]);
        f[2 * i] = u.x * iv; f[2 * i + 1] = u.y * iv;
    }
    float* pr = att + row * SEQ + 8 * t;
    *(float4*)(pr)     = make_float4(f[0], f[1], f[2], f[3]);
    *(float4*)(pr + 4) = make_float4(f[4], f[5], f[6], f[7]);
}

// ======================= generic warp-MMA fp16 GEMM =======================
// AK: 0 = fp16 [m][k] cp.async; 1 = fp32 k-contig (convert in reg);
//     2 = fp32 m-contig source (x layout) -> smem [k][m], ldmatrix.trans
// out_kind: 0 = f32, 1 = fp16, 2 = fp16 exp() + deterministic row partial sums,
//           3 = fp16 scaled by rowscale[bz*HWPX + m]
struct GP {
    const void* A;
    const void* B;
    int K, lda, ldb, ldc;
    long long bsA, bsB, bsC;
    void* C;
    int out_kind;
    const float* bias; int bias_per_m;
    float alpha;
    const void* mask; long long bsMask;
    float* rs;                     // out_kind 2: partial-sum buffer
    const float* rowscale;         // out_kind 3: per-row scale (indexed bz*HWPX+m)
};

#define RS  72
#define RS2 136
#define TILE_B (128 * RS * 2)
#define TG_SMEM (4 * TILE_B)

__device__ __forceinline__ void fill16(uint32_t sbase, const __half* g, int ld, int tid) {
    #pragma unroll
    for (int i = 0; i < 4; i++) {
        int idx = tid + i * 256;
        int r = idx >> 3, c = idx & 7;
        cp_async16(sbase + (r * RS + c * 8) * 2, g + (long long)r * ld + c * 8);
    }
}
__device__ __forceinline__ void fill32k(char* sm, const float* g, int ld, int tid) {
    #pragma unroll
    for (int i = 0; i < 4; i++) {
        int c = tid + i * 256;
        int r = c >> 3, s = c & 7;
        const float4* src = (const float4*)(g + (long long)r * ld + s * 8);
        float4 u = src[0], v = src[1];
        __align__(16) __half2 h[4] = {
            __floats2half2_rn(u.x, u.y), __floats2half2_rn(u.z, u.w),
            __floats2half2_rn(v.x, v.y), __floats2half2_rn(v.z, v.w) };
        *(uint4*)(sm + (r * RS + s * 8) * 2) = *(uint4*)h;
    }
}
__device__ __forceinline__ void fill32t(char* sm, const float* g, int ldk, int tid) {
    #pragma unroll
    for (int i = 0; i < 4; i++) {
        int c = tid + i * 256;
        int r = c >> 4, s = c & 15;
        const float4* src = (const float4*)(g + (long long)r * ldk + s * 8);
        float4 u = src[0], v = src[1];
        __align__(16) __half2 h[4] = {
            __floats2half2_rn(u.x, u.y), __floats2half2_rn(u.z, u.w),
            __floats2half2_rn(v.x, v.y), __floats2half2_rn(v.z, v.w) };
        *(uint4*)(sm + (r * RS2 + s * 8) * 2) = *(uint4*)h;
    }
}

template<int AK>
__global__ void __launch_bounds__(256)
tgemm_kernel(GP p) {
    extern __shared__ char smem_raw[];
    char* smc = smem_raw;
    uint32_t sb = smem_u32(smem_raw);
    const int tid = threadIdx.x, wid = tid >> 5, lane = tid & 31;
    const int bz = blockIdx.z;
    const int m0 = blockIdx.y * 128, n0 = blockIdx.x * 128;
    const int warp_m = wid & 3, warp_n = wid >> 2;

    const int offA[2] = { 0, 2 * TILE_B };
    const int offB[2] = { TILE_B, 3 * TILE_B };

    const __half* Ah = nullptr; const float* Af = nullptr;
    if (AK == 0) Ah = (const __half*)p.A + (long long)bz * p.bsA + (long long)m0 * p.lda;
    else if (AK == 1) Af = (const float*)p.A + (long long)bz * p.bsA + (long long)m0 * p.lda;
    else Af = (const float*)p.A + (long long)bz * p.bsA + m0;
    const __half* Bh = (const __half*)p.B + (long long)bz * p.bsB + (long long)n0 * p.ldb;

    const int total = p.K >> 6;

    uint32_t aOff[2], bOff[4];
    if (AK == 2) {
        int t4 = lane >> 3, r = lane & 7;
        #pragma unroll
        for (int i = 0; i < 2; i++)
            aOff[i] = (((t4 >> 1) * 8 + r) * RS2 + warp_m * 32 + i * 16 + (t4 & 1) * 8) * 2;
    } else {
        #pragma unroll
        for (int i = 0; i < 2; i++)
            aOff[i] = ((warp_m * 32 + i * 16 + (lane & 15)) * RS + ((lane >> 4) << 3)) * 2;
    }
    #pragma unroll
    for (int j = 0; j < 4; j++)
        bOff[j] = ((warp_n * 64 + j * 16 + (lane & 7) + ((lane >> 4) << 3)) * RS
                   + (((lane >> 3) & 1) << 3)) * 2;

    float acc[2][8][4];
    #pragma unroll
    for (int i = 0; i < 2; i++)
        #pragma unroll
        for (int j = 0; j < 8; j++)
            #pragma unroll
            for (int q = 0; q < 4; q++) acc[i][j][q] = 0.f;

    auto fillA = [&](int buf, int k0) {
        if (AK == 0)      fill16(sb + offA[buf], Ah + k0, p.lda, tid);
        else if (AK == 1) fill32k(smc + offA[buf], Af + k0, p.lda, tid);
        else              fill32t(smc + offA[buf], Af + (long long)k0 * p.lda, p.lda, tid);
    };

    fillA(0, 0);
    fill16(sb + offB[0], Bh, p.ldb, tid);
    CP_COMMIT();

    for (int c = 0; c < total; c++) {
        int cur = c & 1;
        if (c + 1 < total) {
            int nb = cur ^ 1, k0 = (c + 1) << 6;
            fillA(nb, k0);
            fill16(sb + offB[nb], Bh + k0, p.ldb, tid);
            CP_COMMIT();
            CP_WAIT1();
        } else {
            CP_WAIT0();
        }
        __syncthreads();

        #pragma unroll
        for (int ks = 0; ks < 4; ks++) {
            uint32_t a[2][4];
            #pragma unroll
            for (int i = 0; i < 2; i++) {
                if (AK == 2) ldsm4t(a[i], sb + offA[cur] + aOff[i] + ks * (16 * RS2 * 2));
                else         ldsm4(a[i], sb + offA[cur] + aOff[i] + ks * 32);
            }
            #pragma unroll
            for (int jn = 0; jn < 4; jn++) {
                uint32_t b[4];
                ldsm4(b, sb + offB[cur] + bOff[jn] + ks * 32);
                #pragma unroll
                for (int i = 0; i < 2; i++) {
                    mma16816(acc[i][2 * jn],     a[i], b[0], b[1]);
                    mma16816(acc[i][2 * jn + 1], a[i], b[2], b[3]);
                }
            }
        }
        __syncthreads();
    }

    // ---- epilogue ----
    const int g = lane >> 2, t = lane & 3;
    const int mmode = p.mask ? g_mask_mode : 0;
    const int rbase = m0 + warp_m * 32;
    const int cbase = n0 + warp_n * 64;

    #pragma unroll
    for (int i = 0; i < 2; i++) {
        #pragma unroll
        for (int rr = 0; rr < 2; rr++) {
            int m = rbase + i * 16 + g + rr * 8;
            float bm = (p.bias && p.bias_per_m) ? p.bias[m] : 0.f;
            float rsc = (p.out_kind == 3) ? p.rowscale[(long long)bz * HWPX + m] : 1.f;
            long long rowoff = (long long)bz * p.bsC + (long long)m * p.ldc;
            long long mrowoff = p.mask ? ((long long)bz * p.bsMask + (long long)m * p.ldc) : 0;
            float s_loc = 0.f;
            #pragma unroll
            for (int j = 0; j < 8; j++) {
                int n = cbase + j * 8 + 2 * t;
                float v0 = acc[i][j][rr * 2 + 0] * p.alpha + bm;
                float v1 = acc[i][j][rr * 2 + 1] * p.alpha + bm;
                if (p.bias && !p.bias_per_m) { v0 += p.bias[n]; v1 += p.bias[n + 1]; }
                if (p.mask) {
                    bool mk0, mk1;
                    if (mmode == 0) {
                        mk0 = ((const unsigned char*)p.mask)[mrowoff + n] != 0;
                        mk1 = ((const unsigned char*)p.mask)[mrowoff + n + 1] != 0;
                    } else if (mmode == 1) {
                        mk0 = ((const int*)p.mask)[mrowoff + n] != 0;
                        mk1 = ((const int*)p.mask)[mrowoff + n + 1] != 0;
                    } else {
                        mk0 = ((const float*)p.mask)[mrowoff + n] != 0.f;
                        mk1 = ((const float*)p.mask)[mrowoff + n + 1] != 0.f;
                    }
                    if (mk0) v0 = -1e9f;
                    if (mk1) v1 = -1e9f;
                }
                if (p.out_kind == 0) {
                    *(float2*)((float*)p.C + rowoff + n) = make_float2(v0, v1);
                } else if (p.out_kind == 1) {
                    __half2 pk;
                    pk.x = __float2half_rn(v0);
                    pk.y = __float2half_rn(v1);
                    *(__half2*)((__half*)p.C + rowoff + n) = pk;
                } else if (p.out_kind == 2) {
                    float e0 = __expf(v0), e1 = __expf(v1);   // masked: exp(-1e9)=0 exactly
                    s_loc += e0 + e1;
                    __half2 pk;
                    pk.x = __float2half_rn(e0);
                    pk.y = __float2half_rn(e1);
                    *(__half2*)((__half*)p.C + rowoff + n) = pk;
                } else {
                    __half2 pk;
                    pk.x = __float2half_rn(v0 * rsc);
                    pk.y = __float2half_rn(v1 * rsc);
                    *(__half2*)((__half*)p.C + rowoff + n) = pk;
                }
            }
            if (p.out_kind == 2) {
                s_loc += __shfl_xor_sync(0xffffffffu, s_loc, 1);
                s_loc += __shfl_xor_sync(0xffffffffu, s_loc, 2);
                if (t == 0)
                    p.rs[((long long)bz * HWPX + m) * 32 + blockIdx.x * 2 + warp_n] = s_loc;
            }
        }
    }
}

// ======================= launch =======================
template<int AK>
static void launch_gemm(const void* A, const void* B,
                        int M, int N, int K, int lda, int ldb, int ldc,
                        long long bsA, long long bsB, long long bsC,
                        void* C, int out_kind,
                        const float* bias, int bias_per_m, float alpha,
                        const void* mask, long long bsMask,
                        float* rs, const float* rowscale) {
    GP p;
    p.A = A; p.B = B;
    p.K = K; p.lda = lda; p.ldb = ldb; p.ldc = ldc;
    p.bsA = bsA; p.bsB = bsB; p.bsC = bsC;
    p.C = C; p.out_kind = out_kind;
    p.bias = bias; p.bias_per_m = bias_per_m; p.alpha = alpha;
    p.mask = mask; p.bsMask = bsMask; p.rs = rs; p.rowscale = rowscale;
    cudaFuncSetAttribute(tgemm_kernel<AK>, cudaFuncAttributeMaxDynamicSharedMemorySize, TG_SMEM);
    dim3 grid(N / 128, M / 128, BATCH);
    tgemm_kernel<AK><<<grid, 256, TG_SMEM>>>(p);
}

extern "C" void kernel_launch(void* const* d_in, const int* in_sizes, int n_in,
                              void* d_out, int out_size) {
    const float* x     = (const float*)d_in[0];
    const float* ctx   = (const float*)d_in[1];
    const void*  mask  = d_in[2];
    const float* W_in  = (const float*)d_in[3];
    const float* b_in  = (const float*)d_in[4];
    const float* Wq    = (const float*)d_in[5];
    const float* bq    = (const float*)d_in[6];
    const float* Wk    = (const float*)d_in[7];
    const float* bk    = (const float*)d_in[8];
    const float* Wv    = (const float*)d_in[9];
    const float* bv    = (const float*)d_in[10];
    const float* W_out = (const float*)d_in[11];
    const float* b_out = (const float*)d_in[12];

    float* out = (float*)d_out;
    float* att = out + (long long)BATCH * INCH * HWPX;

    float *pWeff, *pbeff, *pPart, *pRinv;
    __half *pWeffh, *pWkh, *pWvh, *pWoh, *pCtx16, *pQ, *pK, *pVt, *pEL, *pO;
    cudaGetSymbolAddress((void**)&pWeff, g_Weff);
    cudaGetSymbolAddress((void**)&pbeff, g_beff);
    cudaGetSymbolAddress((void**)&pWeffh, g_Weffh);
    cudaGetSymbolAddress((void**)&pWkh, g_Wkh);
    cudaGetSymbolAddress((void**)&pWvh, g_Wvh);
    cudaGetSymbolAddress((void**)&pWoh, g_Wouth);
    cudaGetSymbolAddress((void**)&pCtx16, g_ctx16);
    cudaGetSymbolAddress((void**)&pQ, g_Q);
    cudaGetSymbolAddress((void**)&pK, g_K);
    cudaGetSymbolAddress((void**)&pVt, g_Vt);
    cudaGetSymbolAddress((void**)&pEL, g_EL);
    cudaGetSymbolAddress((void**)&pO, g_O);
    cudaGetSymbolAddress((void**)&pPart, g_part);
    cudaGetSymbolAddress((void**)&pRinv, g_rinv);

    // weights + converts
    weff_kernel<<<EMB, 256>>>(Wq, W_in, b_in, bq);
    cvt_half_kernel<<<64, 256>>>(pWeffh, pWeff, EMB * INCH);
    cvt_half_kernel<<<64, 256>>>(pWkh, Wk, EMB * CTXD);
    cvt_half_kernel<<<64, 256>>>(pWvh, Wv, EMB * CTXD);
    cvt_half_kernel<<<64, 256>>>(pWoh, W_out, INCH * EMB);
    cvt_half_kernel<<<1024, 256>>>(pCtx16, ctx, BATCH * SEQ * CTXD);
    // mask dtype detection (before logits)
    int scan = 65536;
    if (in_sizes[2] < scan) scan = in_sizes[2];
    detect_mask_kernel<<<1, 256>>>((const unsigned char*)mask, scan);
    // Q-proj: Q[p,e] = x^T[p,c].Weff[e,c] + beff   (A = x fp32 trans path)
    launch_gemm<2>(x, pWeffh, HWPX, EMB, INCH,
                   HWPX, INCH, EMB, (long long)INCH * HWPX, 0, (long long)HWPX * EMB,
                   pQ, 1, pbeff, 0, 1.f, 0, 0, 0, 0);
    // K-proj: K[s,e] = ctx[s,d].Wk[e,d] + bk   (A = ctx fp32 direct)
    launch_gemm<1>(ctx, pWkh, SEQ, EMB, CTXD,
                   CTXD, CTXD, EMB, (long long)SEQ * CTXD, 0, (long long)SEQ * EMB,
                   pK, 1, bk, 0, 1.f, 0, 0, 0, 0);
    // V-proj: Vt[e,s] = Wv[e,d].ctx16[s,d] + bv
    launch_gemm<0>(pWvh, pCtx16, EMB, SEQ, CTXD,
                   CTXD, CTXD, SEQ, 0, (long long)SEQ * CTXD, (long long)EMB * SEQ,
                   pVt, 1, bv, 1, 1.f, 0, 0, 0, 0);
    // logits -> exp(logits) fp16 + deterministic row partial sums
    launch_gemm<0>(pQ, pK, HWPX, SEQ, EMB,
                   EMB, EMB, SEQ, (long long)HWPX * EMB, (long long)SEQ * EMB, (long long)HWPX * SEQ,
                   pEL, 2, 0, 0, 0.0625f, mask, (long long)HWPX * SEQ, pPart, 0);
    // row sums -> inverses
    rowinv_kernel<<<(NROWS + 255) / 256, 256>>>(pPart, pRinv);
    // att fp32 output (pure streaming)
    normatt_kernel<<<NROWS, 256>>>(pEL, pRinv, att);
    // O[p,e] = rinv[p] * (expL[p,s] . Vt[e,s])   (rinv factored into epilogue)
    launch_gemm<0>(pEL, pVt, HWPX, EMB, SEQ,
                   SEQ, SEQ, EMB, (long long)HWPX * SEQ, (long long)EMB * SEQ, (long long)HWPX * EMB,
                   pO, 3, 0, 0, 1.f, 0, 0, 0, pRinv);
    // out-proj: out[c,p] = W_out[c,e].O[p,e] + b_out[c]  (fp32)
    launch_gemm<0>(pWoh, pO, INCH, HWPX, EMB,
                   EMB, EMB, HWPX, 0, (long long)HWPX * EMB, (long long)INCH * HWPX,
                   out, 0, b_out, 1, 1.f, 0, 0, 0, 0);
}

// round 15
// speedup vs baseline: 1.0833x; 1.0522x over previous
#include <cuda_runtime.h>
#include <cuda_fp16.h>
#include <cstdint>

// Problem constants
#define BATCH 16
#define INCH  256
#define HWPX  2304
#define SEQ   2048
#define CTXD  128
#define EMB   256
#define NROWS (BATCH * HWPX)

// ======================= PTX helpers =======================
__device__ __forceinline__ uint32_t smem_u32(const void* p) {
    uint32_t a;
    asm("{ .reg .u64 t; cvta.to.shared.u64 t, %1; cvt.u32.u64 %0, t; }" : "=r"(a) : "l"(p));
    return a;
}
__device__ __forceinline__ void cp_async16(uint32_t dst, const void* src) {
    asm volatile("cp.async.cg.shared.global [%0], [%1], 16;" :: "r"(dst), "l"(src));
}
#define CP_COMMIT() asm volatile("cp.async.commit_group;" ::: "memory")
#define CP_WAIT0()  asm volatile("cp.async.wait_group 0;" ::: "memory")
#define CP_WAIT1()  asm volatile("cp.async.wait_group 1;" ::: "memory")

__device__ __forceinline__ void ldsm4(uint32_t* r, uint32_t addr) {
    asm volatile("ldmatrix.sync.aligned.m8n8.x4.shared.b16 {%0,%1,%2,%3}, [%4];"
        : "=r"(r[0]), "=r"(r[1]), "=r"(r[2]), "=r"(r[3]) : "r"(addr));
}
__device__ __forceinline__ void ldsm4t(uint32_t* r, uint32_t addr) {
    asm volatile("ldmatrix.sync.aligned.m8n8.x4.trans.shared.b16 {%0,%1,%2,%3}, [%4];"
        : "=r"(r[0]), "=r"(r[1]), "=r"(r[2]), "=r"(r[3]) : "r"(addr));
}
__device__ __forceinline__ void mma16816(float* c, const uint32_t* a, uint32_t b0, uint32_t b1) {
    asm volatile("mma.sync.aligned.m16n8k16.row.col.f32.f16.f16.f32 "
        "{%0,%1,%2,%3}, {%4,%5,%6,%7}, {%8,%9}, {%0,%1,%2,%3};"
        : "+f"(c[0]), "+f"(c[1]), "+f"(c[2]), "+f"(c[3])
        : "r"(a[0]), "r"(a[1]), "r"(a[2]), "r"(a[3]), "r"(b0), "r"(b1));
}

// ======================= scratch =======================
__device__ __align__(16) float g_Weff[EMB * INCH];
__device__ __align__(16) float g_beff[EMB];
__device__ __align__(16) __half g_Weffh[EMB * INCH];
__device__ __align__(16) __half g_Wkh[EMB * CTXD];
__device__ __align__(16) __half g_Wvh[EMB * CTXD];
__device__ __align__(16) __half g_Wouth[INCH * EMB];
__device__ __align__(16) __half g_ctx16[BATCH * SEQ * CTXD];
__device__ __align__(16) __half g_Q[BATCH * HWPX * EMB];
__device__ __align__(16) __half g_K[BATCH * SEQ * EMB];
__device__ __align__(16) __half g_Vt[BATCH * EMB * SEQ];
__device__ __align__(16) __half g_A16[(size_t)BATCH * HWPX * SEQ]; // logits, then normalized att fp16
__device__ __align__(16) __half g_O[BATCH * HWPX * EMB];
__device__ int g_mask_mode;

// ======================= mask dtype detection =======================
__global__ void detect_mask_kernel(const unsigned char* __restrict__ m, int nbytes) {
    __shared__ int c1, c23;
    if (threadIdx.x == 0) { c1 = 0; c23 = 0; }
    __syncthreads();
    int l1 = 0, l23 = 0;
    for (int i = threadIdx.x; i < nbytes; i += blockDim.x) {
        unsigned char v = m[i];
        if (v) { int r = i & 3; if (r == 1) l1++; else if (r >= 2) l23++; }
    }
    if (l1) atomicAdd(&c1, l1);
    if (l23) atomicAdd(&c23, l23);
    __syncthreads();
    if (threadIdx.x == 0) g_mask_mode = (c1 > 0) ? 0 : ((c23 > 0) ? 2 : 1);
}

// ======================= Weff = Wq @ W_in (fp32) =======================
__global__ void weff_kernel(const float* __restrict__ Wq, const float* __restrict__ W_in,
                            const float* __restrict__ b_in, const float* __restrict__ bq) {
    __shared__ float wqs[EMB];
    int e = blockIdx.x, c = threadIdx.x;
    wqs[c] = Wq[e * EMB + c];
    __syncthreads();
    float s = 0.f;
    #pragma unroll 8
    for (int f = 0; f < EMB; f++) s += wqs[f] * W_in[f * INCH + c];
    g_Weff[e * INCH + c] = s;
    if (c == 0) {
        float sb = 0.f;
        for (int f = 0; f < EMB; f++) sb += wqs[f] * b_in[f];
        g_beff[e] = sb + bq[e];
    }
}

// Fused weight convert: Weff(65536) + Wk(32768) + Wv(32768) + Wout(65536) in one launch
#define CW_N0 (EMB * INCH)
#define CW_N1 (CW_N0 + EMB * CTXD)
#define CW_N2 (CW_N1 + EMB * CTXD)
#define CW_N3 (CW_N2 + INCH * EMB)
__global__ void cvt_weights_kernel(const float* __restrict__ Wk, const float* __restrict__ Wv,
                                   const float* __restrict__ Wout) {
    for (int i = blockIdx.x * blockDim.x + threadIdx.x; i < CW_N3; i += gridDim.x * blockDim.x) {
        if (i < CW_N0)       g_Weffh[i] = __float2half_rn(g_Weff[i]);
        else if (i < CW_N1)  g_Wkh[i - CW_N0] = __float2half_rn(Wk[i - CW_N0]);
        else if (i < CW_N2)  g_Wvh[i - CW_N1] = __float2half_rn(Wv[i - CW_N1]);
        else                 g_Wouth[i - CW_N2] = __float2half_rn(Wout[i - CW_N2]);
    }
}
__global__ void cvt_half_kernel(__half* __restrict__ d, const float* __restrict__ s, int n) {
    for (int i = blockIdx.x * blockDim.x + threadIdx.x; i < n; i += gridDim.x * blockDim.x)
        d[i] = __float2half_rn(s[i]);
}

// ======================= generic warp-MMA fp16 GEMM =======================
// AK: 0 = fp16 [m][k] cp.async; 1 = fp32 k-contig (convert in reg);
//     2 = fp32 m-contig source (x layout) -> smem [k][m], ldmatrix.trans
// out_kind: 0 = f32, 1 = fp16
struct GP {
    const void* A;
    const void* B;
    int K, lda, ldb, ldc;
    long long bsA, bsB, bsC;
    void* C;
    int out_kind;
    const float* bias; int bias_per_m;
    float alpha;
    const void* mask; long long bsMask;
};

#define RS  72
#define RS2 136
#define TILE_B (128 * RS * 2)
#define TG_SMEM (4 * TILE_B)

__device__ __forceinline__ void fill16(uint32_t sbase, const __half* g, int ld, int tid) {
    #pragma unroll
    for (int i = 0; i < 4; i++) {
        int idx = tid + i * 256;
        int r = idx >> 3, c = idx & 7;
        cp_async16(sbase + (r * RS + c * 8) * 2, g + (long long)r * ld + c * 8);
    }
}
__device__ __forceinline__ void fill32k(char* sm, const float* g, int ld, int tid) {
    #pragma unroll
    for (int i = 0; i < 4; i++) {
        int c = tid + i * 256;
        int r = c >> 3, s = c & 7;
        const float4* src = (const float4*)(g + (long long)r * ld + s * 8);
        float4 u = src[0], v = src[1];
        __align__(16) __half2 h[4] = {
            __floats2half2_rn(u.x, u.y), __floats2half2_rn(u.z, u.w),
            __floats2half2_rn(v.x, v.y), __floats2half2_rn(v.z, v.w) };
        *(uint4*)(sm + (r * RS + s * 8) * 2) = *(uint4*)h;
    }
}
__device__ __forceinline__ void fill32t(char* sm, const float* g, int ldk, int tid) {
    #pragma unroll
    for (int i = 0; i < 4; i++) {
        int c = tid + i * 256;
        int r = c >> 4, s = c & 15;
        const float4* src = (const float4*)(g + (long long)r * ldk + s * 8);
        float4 u = src[0], v = src[1];
        __align__(16) __half2 h[4] = {
            __floats2half2_rn(u.x, u.y), __floats2half2_rn(u.z, u.w),
            __floats2half2_rn(v.x, v.y), __floats2half2_rn(v.z, v.w) };
        *(uint4*)(sm + (r * RS2 + s * 8) * 2) = *(uint4*)h;
    }
}

// __launch_bounds__(256, 2): cap regs at 128 so 2 CTAs co-reside per SM
// (2 x 73.7KB smem = 147KB < 227KB). Doubles resident warps 8 -> 16 so one
// CTA's fill/sync/epilogue overlaps the other's MMAs.
template<int AK>
__global__ void __launch_bounds__(256, 2)
tgemm_kernel(GP p) {
    extern __shared__ char smem_raw[];
    char* smc = smem_raw;
    uint32_t sb = smem_u32(smem_raw);
    const int tid = threadIdx.x, wid = tid >> 5, lane = tid & 31;
    const int bz = blockIdx.z;
    const int m0 = blockIdx.y * 128, n0 = blockIdx.x * 128;
    const int warp_m = wid & 3, warp_n = wid >> 2;

    const int offA[2] = { 0, 2 * TILE_B };
    const int offB[2] = { TILE_B, 3 * TILE_B };

    const __half* Ah = nullptr; const float* Af = nullptr;
    if (AK == 0) Ah = (const __half*)p.A + (long long)bz * p.bsA + (long long)m0 * p.lda;
    else if (AK == 1) Af = (const float*)p.A + (long long)bz * p.bsA + (long long)m0 * p.lda;
    else Af = (const float*)p.A + (long long)bz * p.bsA + m0;
    const __half* Bh = (const __half*)p.B + (long long)bz * p.bsB + (long long)n0 * p.ldb;

    const int total = p.K >> 6;

    uint32_t aOff[2], bOff[4];
    if (AK == 2) {
        int t4 = lane >> 3, r = lane & 7;
        #pragma unroll
        for (int i = 0; i < 2; i++)
            aOff[i] = (((t4 >> 1) * 8 + r) * RS2 + warp_m * 32 + i * 16 + (t4 & 1) * 8) * 2;
    } else {
        #pragma unroll
        for (int i = 0; i < 2; i++)
            aOff[i] = ((warp_m * 32 + i * 16 + (lane & 15)) * RS + ((lane >> 4) << 3)) * 2;
    }
    #pragma unroll
    for (int j = 0; j < 4; j++)
        bOff[j] = ((warp_n * 64 + j * 16 + (lane & 7) + ((lane >> 4) << 3)) * RS
                   + (((lane >> 3) & 1) << 3)) * 2;

    float acc[2][8][4];
    #pragma unroll
    for (int i = 0; i < 2; i++)
        #pragma unroll
        for (int j = 0; j < 8; j++)
            #pragma unroll
            for (int q = 0; q < 4; q++) acc[i][j][q] = 0.f;

    auto fillA = [&](int buf, int k0) {
        if (AK == 0)      fill16(sb + offA[buf], Ah + k0, p.lda, tid);
        else if (AK == 1) fill32k(smc + offA[buf], Af + k0, p.lda, tid);
        else              fill32t(smc + offA[buf], Af + (long long)k0 * p.lda, p.lda, tid);
    };

    fillA(0, 0);
    fill16(sb + offB[0], Bh, p.ldb, tid);
    CP_COMMIT();

    for (int c = 0; c < total; c++) {
        int cur = c & 1;
        if (c + 1 < total) {
            int nb = cur ^ 1, k0 = (c + 1) << 6;
            fillA(nb, k0);
            fill16(sb + offB[nb], Bh + k0, p.ldb, tid);
            CP_COMMIT();
            CP_WAIT1();
        } else {
            CP_WAIT0();
        }
        __syncthreads();

        #pragma unroll
        for (int ks = 0; ks < 4; ks++) {
            uint32_t a[2][4];
            #pragma unroll
            for (int i = 0; i < 2; i++) {
                if (AK == 2) ldsm4t(a[i], sb + offA[cur] + aOff[i] + ks * (16 * RS2 * 2));
                else         ldsm4(a[i], sb + offA[cur] + aOff[i] + ks * 32);
            }
            #pragma unroll
            for (int jn = 0; jn < 4; jn++) {
                uint32_t b[4];
                ldsm4(b, sb + offB[cur] + bOff[jn] + ks * 32);
                #pragma unroll
                for (int i = 0; i < 2; i++) {
                    mma16816(acc[i][2 * jn],     a[i], b[0], b[1]);
                    mma16816(acc[i][2 * jn + 1], a[i], b[2], b[3]);
                }
            }
        }
        __syncthreads();
    }

    // ---- epilogue ----
    const int g = lane >> 2, t = lane & 3;
    const int mmode = p.mask ? g_mask_mode : 0;
    const int rbase = m0 + warp_m * 32;
    const int cbase = n0 + warp_n * 64;

    #pragma unroll
    for (int i = 0; i < 2; i++) {
        #pragma unroll
        for (int rr = 0; rr < 2; rr++) {
            int m = rbase + i * 16 + g + rr * 8;
            float bm = (p.bias && p.bias_per_m) ? p.bias[m] : 0.f;
            long long rowoff = (long long)bz * p.bsC + (long long)m * p.ldc;
            long long mrowoff = p.mask ? ((long long)bz * p.bsMask + (long long)m * p.ldc) : 0;
            #pragma unroll
            for (int j = 0; j < 8; j++) {
                int n = cbase + j * 8 + 2 * t;
                float v0 = acc[i][j][rr * 2 + 0] * p.alpha + bm;
                float v1 = acc[i][j][rr * 2 + 1] * p.alpha + bm;
                if (p.bias && !p.bias_per_m) { v0 += p.bias[n]; v1 += p.bias[n + 1]; }
                if (p.mask) {
                    bool mk0, mk1;
                    if (mmode == 0) {
                        mk0 = ((const unsigned char*)p.mask)[mrowoff + n] != 0;
                        mk1 = ((const unsigned char*)p.mask)[mrowoff + n + 1] != 0;
                    } else if (mmode == 1) {
                        mk0 = ((const int*)p.mask)[mrowoff + n] != 0;
                        mk1 = ((const int*)p.mask)[mrowoff + n + 1] != 0;
                    } else {
                        mk0 = ((const float*)p.mask)[mrowoff + n] != 0.f;
                        mk1 = ((const float*)p.mask)[mrowoff + n + 1] != 0.f;
                    }
                    if (mk0) v0 = -1e9f;
                    if (mk1) v1 = -1e9f;
                }
                if (p.out_kind == 0) {
                    *(float2*)((float*)p.C + rowoff + n) = make_float2(v0, v1);
                } else {
                    __half2 pk;
                    pk.x = __float2half_rn(v0);
                    pk.y = __float2half_rn(v1);
                    *(__half2*)((__half*)p.C + rowoff + n) = pk;
                }
            }
        }
    }
}

// ======================= softmax: fp16 logits -> fp32 att + fp16 normalized (in place) =======================
// Each thread owns 8 contiguous elements [8t .. 8t+7] of the row.
__global__ void __launch_bounds__(256) softmax_kernel(const __half* __restrict__ logits_in,
                                                      float* __restrict__ att,
                                                      __half* __restrict__ a16) {
    __shared__ float red[8];
    long long row = blockIdx.x;
    const int t = threadIdx.x;
    const __half* lr = logits_in + row * SEQ;
    uint4 raw = ((const uint4*)lr)[t];
    __half2* hp = (__half2*)&raw;
    float x[8];
    #pragma unroll
    for (int i = 0; i < 4; i++) {
        float2 f = __half22float2(hp[i]);
        x[2 * i] = f.x; x[2 * i + 1] = f.y;
    }

    float m = x[0];
    #pragma unroll
    for (int i = 1; i < 8; i++) m = fmaxf(m, x[i]);
    #pragma unroll
    for (int o = 16; o; o >>= 1) m = fmaxf(m, __shfl_xor_sync(0xffffffffu, m, o));
    if ((t & 31) == 0) red[t >> 5] = m;
    __syncthreads();
    float mm = red[0];
    #pragma unroll
    for (int i = 1; i < 8; i++) mm = fmaxf(mm, red[i]);
    __syncthreads();

    float e[8], s = 0.f;
    #pragma unroll
    for (int i = 0; i < 8; i++) { e[i] = __expf(x[i] - mm); s += e[i]; }
    #pragma unroll
    for (int o = 16; o; o >>= 1) s += __shfl_xor_sync(0xffffffffu, s, o);
    if ((t & 31) == 0) red[t >> 5] = s;
    __syncthreads();
    float ss = red[0];
    #pragma unroll
    for (int i = 1; i < 8; i++) ss += red[i];
    float inv = 1.f / ss;

    float r8[8];
    #pragma unroll
    for (int i = 0; i < 8; i++) r8[i] = e[i] * inv;

    float* pr = att + row * SEQ;
    *(float4*)(pr + 8 * t)     = make_float4(r8[0], r8[1], r8[2], r8[3]);
    *(float4*)(pr + 8 * t + 4) = make_float4(r8[4], r8[5], r8[6], r8[7]);

    __align__(16) __half2 h2[4];
    #pragma unroll
    for (int i = 0; i < 4; i++) {
        h2[i].x = __float2half_rn(r8[2 * i]);
        h2[i].y = __float2half_rn(r8[2 * i + 1]);
    }
    ((uint4*)(a16 + row * SEQ))[t] = *(uint4*)h2;
}

// ======================= launch =======================
template<int AK>
static void launch_gemm(const void* A, const void* B,
                        int M, int N, int K, int lda, int ldb, int ldc,
                        long long bsA, long long bsB, long long bsC,
                        void* C, int out_kind,
                        const float* bias, int bias_per_m, float alpha,
                        const void* mask, long long bsMask) {
    GP p;
    p.A = A; p.B = B;
    p.K = K; p.lda = lda; p.ldb = ldb; p.ldc = ldc;
    p.bsA = bsA; p.bsB = bsB; p.bsC = bsC;
    p.C = C; p.out_kind = out_kind;
    p.bias = bias; p.bias_per_m = bias_per_m; p.alpha = alpha;
    p.mask = mask; p.bsMask = bsMask;
    cudaFuncSetAttribute(tgemm_kernel<AK>, cudaFuncAttributeMaxDynamicSharedMemorySize, TG_SMEM);
    dim3 grid(N / 128, M / 128, BATCH);
    tgemm_kernel<AK><<<grid, 256, TG_SMEM>>>(p);
}

extern "C" void kernel_launch(void* const* d_in, const int* in_sizes, int n_in,
                              void* d_out, int out_size) {
    const float* x     = (const float*)d_in[0];
    const float* ctx   = (const float*)d_in[1];
    const void*  mask  = d_in[2];
    const float* W_in  = (const float*)d_in[3];
    const float* b_in  = (const float*)d_in[4];
    const float* Wq    = (const float*)d_in[5];
    const float* bq    = (const float*)d_in[6];
    const float* Wk    = (const float*)d_in[7];
    const float* bk    = (const float*)d_in[8];
    const float* Wv    = (const float*)d_in[9];
    const float* bv    = (const float*)d_in[10];
    const float* W_out = (const float*)d_in[11];
    const float* b_out = (const float*)d_in[12];

    float* out = (float*)d_out;
    float* att = out + (long long)BATCH * INCH * HWPX;

    float *pWeff, *pbeff;
    __half *pWeffh, *pWkh, *pWvh, *pWoh, *pCtx16, *pQ, *pK, *pVt, *pA16, *pO;
    cudaGetSymbolAddress((void**)&pWeff, g_Weff);
    cudaGetSymbolAddress((void**)&pbeff, g_beff);
    cudaGetSymbolAddress((void**)&pWeffh, g_Weffh);
    cudaGetSymbolAddress((void**)&pWkh, g_Wkh);
    cudaGetSymbolAddress((void**)&pWvh, g_Wvh);
    cudaGetSymbolAddress((void**)&pWoh, g_Wouth);
    cudaGetSymbolAddress((void**)&pCtx16, g_ctx16);
    cudaGetSymbolAddress((void**)&pQ, g_Q);
    cudaGetSymbolAddress((void**)&pK, g_K);
    cudaGetSymbolAddress((void**)&pVt, g_Vt);
    cudaGetSymbolAddress((void**)&pA16, g_A16);
    cudaGetSymbolAddress((void**)&pO, g_O);

    // 0: mask dtype detection
    int scan = 65536;
    if (in_sizes[2] < scan) scan = in_sizes[2];
    detect_mask_kernel<<<1, 256>>>((const unsigned char*)mask, scan);
    // 1: Weff = Wq @ W_in
    weff_kernel<<<EMB, 256>>>(Wq, W_in, b_in, bq);
    // 2: all weight converts fused
    cvt_weights_kernel<<<128, 256>>>(Wk, Wv, W_out);
    // 3: ctx convert
    cvt_half_kernel<<<1024, 256>>>(pCtx16, ctx, BATCH * SEQ * CTXD);
    // 4: Q-proj: Q[p,e] = x^T[p,c].Weff[e,c] + beff   (A = x fp32 trans path)
    launch_gemm<2>(x, pWeffh, HWPX, EMB, INCH,
                   HWPX, INCH, EMB, (long long)INCH * HWPX, 0, (long long)HWPX * EMB,
                   pQ, 1, pbeff, 0, 1.f, 0, 0);
    // 5: K-proj (profile slot): K[s,e] = ctx[s,d].Wk[e,d] + bk
    launch_gemm<1>(ctx, pWkh, SEQ, EMB, CTXD,
                   CTXD, CTXD, EMB, (long long)SEQ * CTXD, 0, (long long)SEQ * EMB,
                   pK, 1, bk, 0, 1.f, 0, 0);
    // 6: V-proj: Vt[e,s] = Wv[e,d].ctx16[s,d] + bv
    launch_gemm<0>(pWvh, pCtx16, EMB, SEQ, CTXD,
                   CTXD, CTXD, SEQ, 0, (long long)SEQ * CTXD, (long long)EMB * SEQ,
                   pVt, 1, bv, 1, 1.f, 0, 0);
    // 7: logits fp16 + mask -> g_A16
    launch_gemm<0>(pQ, pK, HWPX, SEQ, EMB,
                   EMB, EMB, SEQ, (long long)HWPX * EMB, (long long)SEQ * EMB, (long long)HWPX * SEQ,
                   pA16, 1, 0, 0, 0.0625f, mask, (long long)HWPX * SEQ);
    // 8: softmax: fp16 logits -> fp32 att (d_out) + fp16 normalized (in place)
    softmax_kernel<<<NROWS, 256>>>(pA16, att, pA16);
    // 9: O[p,e] = att[p,s].Vt[e,s]
    launch_gemm<0>(pA16, pVt, HWPX, EMB, SEQ,
                   SEQ, SEQ, EMB, (long long)HWPX * SEQ, (long long)EMB * SEQ, (long long)HWPX * EMB,
                   pO, 1, 0, 0, 1.f, 0, 0);
    // 10: out-proj: out[c,p] = W_out[c,e].O[p,e] + b_out[c]  (fp32)
    launch_gemm<0>(pWoh, pO, INCH, HWPX, EMB,
                   EMB, EMB, HWPX, 0, (long long)HWPX * EMB, (long long)INCH * HWPX,
                   out, 0, b_out, 1, 1.f, 0, 0);
}